// round 3
// baseline (speedup 1.0000x reference)
#include <cuda_runtime.h>
#include <cstddef>

#define NN 100000
#define EE 1600000
#define GG 512
#define DD 64

// ---------------- scratch (static __device__, no allocation) ----------------
__device__ float g_h[(size_t)NN * DD];
__device__ float g_a[(size_t)NN * DD];
__device__ float g_z[(size_t)NN * DD];
__device__ float g_degw[NN];
__device__ float g_psum[GG * DD];
__device__ float g_pcnt[GG];
__device__ int   g_src[EE];
__device__ int   g_dst[EE];
__device__ int   g_batch[NN];
__device__ int   g_eflag;   // nonzero -> edge_index stored as int32
__device__ int   g_bflag;   // nonzero -> batch stored as int32

// ---------------- dtype detection ----------------
// int64 data with values < 2^31 has all-zero odd 32-bit words; int32 data doesn't.
__global__ void detect_kernel(const int* __restrict__ ei32,
                              const int* __restrict__ b32,
                              int* __restrict__ eflag, int* __restrict__ bflag) {
    __shared__ int se, sb;
    if (threadIdx.x == 0) { se = 0; sb = 0; }
    __syncthreads();
    int e = 0, b = 0;
    for (int i = threadIdx.x; i < 1024; i += blockDim.x) {
        e |= ei32[2 * i + 1];                 // safe: >= 2*EE words either way
        b |= b32[NN / 2 + 2 * i + 1];         // word idx < NN: safe either way
    }
    if (e) atomicOr(&se, 1);
    if (b) atomicOr(&sb, 1);
    __syncthreads();
    if (threadIdx.x == 0) { *eflag = se; *bflag = sb; }
}

// ---------------- normalize indices to int32 ----------------
__global__ void cvt_edges_kernel(const int* __restrict__ ei32,
                                 int* __restrict__ src, int* __restrict__ dst,
                                 const int* __restrict__ eflag) {
    int e = blockIdx.x * blockDim.x + threadIdx.x;
    if (e >= EE) return;
    if (*eflag) {                 // int32 layout: [2, E] int32
        src[e] = ei32[e];
        dst[e] = ei32[EE + e];
    } else {                      // int64 layout: lo word of each entry
        src[e] = ei32[2 * (size_t)e];
        dst[e] = ei32[2 * ((size_t)EE + e)];
    }
}

__global__ void cvt_batch_kernel(const int* __restrict__ b32,
                                 int* __restrict__ batch,
                                 const int* __restrict__ bflag) {
    int n = blockIdx.x * blockDim.x + threadIdx.x;
    if (n >= NN) return;
    batch[n] = (*bflag) ? b32[n] : b32[2 * n];
}

// ---------------- deg_w = segment_sum(edge_attr, dst) ----------------
__global__ void deg_kernel(const int* __restrict__ dst,
                           const float* __restrict__ ea,
                           float* __restrict__ degw) {
    int e = blockIdx.x * blockDim.x + threadIdx.x;
    if (e >= EE) return;
    int d = dst[e];
    asm volatile("red.global.add.f32 [%0], %1;" :: "l"(degw + d), "f"(ea[e]) : "memory");
}

// ---------------- h = x @ W_emb + b_emb  (x: [N,4], W_emb: [4,64]) ----------------
__global__ void embed_kernel(const float* __restrict__ x,
                             const float* __restrict__ Wemb,
                             const float* __restrict__ bemb,
                             float* __restrict__ h) {
    int t = blockIdx.x * blockDim.x + threadIdx.x;
    if (t >= NN * 16) return;
    int n = t >> 4;
    int q = t & 15;           // handles dims 4q..4q+3
    float4 xv = ((const float4*)x)[n];
    const float4* W4 = (const float4*)Wemb;   // [4][16] float4 rows
    float4 w0 = W4[0 * 16 + q];
    float4 w1 = W4[1 * 16 + q];
    float4 w2 = W4[2 * 16 + q];
    float4 w3 = W4[3 * 16 + q];
    float4 bb = ((const float4*)bemb)[q];
    float4 o;
    o.x = bb.x + xv.x * w0.x + xv.y * w1.x + xv.z * w2.x + xv.w * w3.x;
    o.y = bb.y + xv.x * w0.y + xv.y * w1.y + xv.z * w2.y + xv.w * w3.y;
    o.z = bb.z + xv.x * w0.z + xv.y * w1.z + xv.z * w2.z + xv.w * w3.z;
    o.w = bb.w + xv.x * w0.w + xv.y * w1.w + xv.z * w2.w + xv.w * w3.w;
    ((float4*)h)[(size_t)n * 16 + q] = o;
}

// ---------------- fused per-layer GEMMs ----------------
// a = h@W1 + b1
// z = h@W3 + b3 - deg_w ⊙ (h@W2)        (scatter target init)
// 512 threads, 128 nodes/block. f32x2 packed FMA: accumulator packs 2 nodes.
__global__ __launch_bounds__(512) void gemm3_kernel(
    const float* __restrict__ h,
    const float* __restrict__ W1, const float* __restrict__ b1,
    const float* __restrict__ W2,
    const float* __restrict__ W3, const float* __restrict__ b3,
    const float* __restrict__ degw,
    float* __restrict__ a_out, float* __restrict__ z_out) {
    __shared__ __align__(16) float hT[64][128];   // transposed h tile (32KB)
    __shared__ __align__(16) float sW[64][64];    // one weight matrix (16KB)
    const int tid = threadIdx.x;
    const int nodeBase = blockIdx.x * 128;

    // load h tile transposed: hT[k][n_local]
    {
        const int n = tid & 127;
        const int kq = tid >> 7;              // 0..3 -> 16 k's each
        const int gn = nodeBase + n;
        #pragma unroll
        for (int kk = 0; kk < 4; kk++) {
            const int k4 = kq * 16 + kk * 4;
            float4 v = make_float4(0.f, 0.f, 0.f, 0.f);
            if (gn < NN) v = *(const float4*)(h + (size_t)gn * 64 + k4);
            hT[k4 + 0][n] = v.x;
            hT[k4 + 1][n] = v.y;
            hT[k4 + 2][n] = v.z;
            hT[k4 + 3][n] = v.w;
        }
    }

    const int tx = tid & 63;   // output dim
    const int ty = tid >> 6;   // 0..7, node group
    const int nb = ty * 16;    // node offset in tile (16 nodes per thread, 8 pairs)

    unsigned long long bacc[8];   // h@W2 results, held across mat passes

    #pragma unroll 1
    for (int m = 0; m < 3; m++) {
        const float* Wm = (m == 0) ? W1 : (m == 1) ? W2 : W3;
        __syncthreads();
        #pragma unroll
        for (int i = 0; i < 2; i++)
            ((float4*)sW)[tid + i * 512] = ((const float4*)Wm)[tid + i * 512];
        __syncthreads();

        unsigned long long acc[8];
        #pragma unroll
        for (int p = 0; p < 8; p++) acc[p] = 0ULL;

        #pragma unroll 8
        for (int k = 0; k < 64; k++) {
            float w = sW[k][tx];
            unsigned long long ws;
            asm("mov.b64 %0, {%1, %1};" : "=l"(ws) : "f"(w));
            #pragma unroll
            for (int i = 0; i < 4; i++) {
                ulonglong2 hv = *(const ulonglong2*)&hT[k][nb + 4 * i];
                asm("fma.rn.f32x2 %0, %1, %2, %0;" : "+l"(acc[2 * i])     : "l"(ws), "l"(hv.x));
                asm("fma.rn.f32x2 %0, %1, %2, %0;" : "+l"(acc[2 * i + 1]) : "l"(ws), "l"(hv.y));
            }
        }

        if (m == 0) {
            const float bias = b1[tx];
            #pragma unroll
            for (int p = 0; p < 8; p++) {
                float f0, f1;
                asm("mov.b64 {%0, %1}, %2;" : "=f"(f0), "=f"(f1) : "l"(acc[p]));
                const int n = nodeBase + nb + 2 * p;
                if (n < NN)     a_out[(size_t)n * 64 + tx]       = f0 + bias;
                if (n + 1 < NN) a_out[(size_t)(n + 1) * 64 + tx] = f1 + bias;
            }
        } else if (m == 1) {
            #pragma unroll
            for (int p = 0; p < 8; p++) bacc[p] = acc[p];
        } else {
            const float bias = b3[tx];
            #pragma unroll
            for (int p = 0; p < 8; p++) {
                float f0, f1, g0, g1;
                asm("mov.b64 {%0, %1}, %2;" : "=f"(f0), "=f"(f1) : "l"(acc[p]));
                asm("mov.b64 {%0, %1}, %2;" : "=f"(g0), "=f"(g1) : "l"(bacc[p]));
                const int n = nodeBase + nb + 2 * p;
                if (n < NN) {
                    float dw = degw[n];
                    z_out[(size_t)n * 64 + tx] = f0 + bias - dw * g0;
                }
                if (n + 1 < NN) {
                    float dw = degw[n + 1];
                    z_out[(size_t)(n + 1) * 64 + tx] = f1 + bias - dw * g1;
                }
            }
        }
    }
}

// ---------------- scatter: z[dst] += w * a[src] ----------------
// 16 lanes per edge, vector reductions (red.global.add.v4.f32).
__global__ void scatter_kernel(const int* __restrict__ srcA,
                               const int* __restrict__ dstA,
                               const float* __restrict__ ea,
                               const float* __restrict__ a,
                               float* __restrict__ z) {
    long long t = (long long)blockIdx.x * blockDim.x + threadIdx.x;
    int e = (int)(t >> 4);
    if (e >= EE) return;
    int lane = (int)(t & 15);
    int src = srcA[e];
    int dst = dstA[e];
    float w = __ldg(ea + e);
    float4 v = *(const float4*)(a + (size_t)src * 64 + lane * 4);
    float* p = z + (size_t)dst * 64 + lane * 4;
    asm volatile("red.global.add.v4.f32 [%0], {%1, %2, %3, %4};"
                 :: "l"(p), "f"(w * v.x), "f"(w * v.y), "f"(w * v.z), "f"(w * v.w)
                 : "memory");
}

// ---------------- h = relu(z) ----------------
__global__ void relu_kernel(const float* __restrict__ z, float* __restrict__ h) {
    int i = blockIdx.x * blockDim.x + threadIdx.x;
    if (i >= NN * 16) return;
    float4 v = ((const float4*)z)[i];
    v.x = fmaxf(v.x, 0.f);
    v.y = fmaxf(v.y, 0.f);
    v.z = fmaxf(v.z, 0.f);
    v.w = fmaxf(v.w, 0.f);
    ((float4*)h)[i] = v;
}

// ---------------- global mean pool (sums + counts) ----------------
__global__ void pool_kernel(const float* __restrict__ h,
                            const int* __restrict__ batch,
                            float* __restrict__ psum, float* __restrict__ pcnt) {
    int t = blockIdx.x * blockDim.x + threadIdx.x;
    if (t >= NN * 16) return;
    int n = t >> 4;
    int q = t & 15;
    int g = batch[n];
    float4 v = ((const float4*)h)[(size_t)n * 16 + q];
    float* p = psum + (size_t)g * 64 + q * 4;
    asm volatile("red.global.add.v4.f32 [%0], {%1, %2, %3, %4};"
                 :: "l"(p), "f"(v.x), "f"(v.y), "f"(v.z), "f"(v.w) : "memory");
    if (q == 0)
        asm volatile("red.global.add.f32 [%0], %1;" :: "l"(pcnt + g), "f"(1.0f) : "memory");
}

// ---------------- final MLP head ----------------
__global__ void mlp_kernel(const float* __restrict__ psum,
                           const float* __restrict__ pcnt,
                           const float* __restrict__ Wl1, const float* __restrict__ bl1,
                           const float* __restrict__ Wl2, const float* __restrict__ bl2,
                           float* __restrict__ out) {
    __shared__ float sW1[64 * 32];
    __shared__ float sW2[32 * 3];
    __shared__ float sb1[32];
    __shared__ float sb2[3];
    int tid = threadIdx.x;
    for (int i = tid; i < 64 * 32; i += blockDim.x) sW1[i] = Wl1[i];
    for (int i = tid; i < 32 * 3; i += blockDim.x) sW2[i] = Wl2[i];
    if (tid < 32) sb1[tid] = bl1[tid];
    if (tid < 3) sb2[tid] = bl2[tid];
    __syncthreads();

    int g = blockIdx.x * blockDim.x + tid;
    if (g >= GG) return;
    float inv = 1.0f / fmaxf(pcnt[g], 1.0f);
    float hid[32];
    #pragma unroll
    for (int j = 0; j < 32; j++) hid[j] = sb1[j];
    #pragma unroll 8
    for (int k = 0; k < 64; k++) {
        float xv = psum[(size_t)g * 64 + k] * inv;
        #pragma unroll
        for (int j = 0; j < 32; j++) hid[j] += xv * sW1[k * 32 + j];
    }
    #pragma unroll
    for (int j = 0; j < 32; j++) hid[j] = fmaxf(hid[j], 0.f);
    #pragma unroll
    for (int c = 0; c < 3; c++) {
        float o = sb2[c];
        #pragma unroll
        for (int j = 0; j < 32; j++) o += hid[j] * sW2[j * 3 + c];
        out[g * 3 + c] = o;
    }
}

// ---------------- launch ----------------
extern "C" void kernel_launch(void* const* d_in, const int* in_sizes, int n_in,
                              void* d_out, int out_size) {
    const float* x        = (const float*)d_in[0];
    const int*   ei32     = (const int*)d_in[1];
    const float* ea       = (const float*)d_in[2];
    const int*   b32      = (const int*)d_in[3];
    const float* Wemb     = (const float*)d_in[4];
    const float* bemb     = (const float*)d_in[5];
    const float* W1       = (const float*)d_in[6];
    const float* b1       = (const float*)d_in[7];
    const float* W2       = (const float*)d_in[8];
    const float* W3       = (const float*)d_in[9];
    const float* b3       = (const float*)d_in[10];
    const float* Wl1      = (const float*)d_in[11];
    const float* bl1      = (const float*)d_in[12];
    const float* Wl2      = (const float*)d_in[13];
    const float* bl2      = (const float*)d_in[14];
    float* out = (float*)d_out;

    float *hp, *ap, *zp, *dwp, *psp, *pcp;
    int *srcp, *dstp, *bp, *efp, *bfp;
    cudaGetSymbolAddress((void**)&hp, g_h);
    cudaGetSymbolAddress((void**)&ap, g_a);
    cudaGetSymbolAddress((void**)&zp, g_z);
    cudaGetSymbolAddress((void**)&dwp, g_degw);
    cudaGetSymbolAddress((void**)&psp, g_psum);
    cudaGetSymbolAddress((void**)&pcp, g_pcnt);
    cudaGetSymbolAddress((void**)&srcp, g_src);
    cudaGetSymbolAddress((void**)&dstp, g_dst);
    cudaGetSymbolAddress((void**)&bp, g_batch);
    cudaGetSymbolAddress((void**)&efp, g_eflag);
    cudaGetSymbolAddress((void**)&bfp, g_bflag);

    cudaMemsetAsync(dwp, 0, NN * sizeof(float));
    cudaMemsetAsync(psp, 0, GG * DD * sizeof(float));
    cudaMemsetAsync(pcp, 0, GG * sizeof(float));

    detect_kernel<<<1, 256>>>(ei32, b32, efp, bfp);
    cvt_edges_kernel<<<(EE + 255) / 256, 256>>>(ei32, srcp, dstp, efp);
    cvt_batch_kernel<<<(NN + 255) / 256, 256>>>(b32, bp, bfp);

    deg_kernel<<<(EE + 255) / 256, 256>>>(dstp, ea, dwp);
    embed_kernel<<<(NN * 16 + 255) / 256, 256>>>(x, Wemb, bemb, hp);

    const int gemmBlocks = (NN + 127) / 128;
    const long long scatterThreads = (long long)EE * 16;
    const int scatterBlocks = (int)((scatterThreads + 255) / 256);

    for (int l = 0; l < 3; l++) {
        gemm3_kernel<<<gemmBlocks, 512>>>(hp,
                                          W1 + (size_t)l * DD * DD, b1 + (size_t)l * DD,
                                          W2 + (size_t)l * DD * DD,
                                          W3 + (size_t)l * DD * DD, b3 + (size_t)l * DD,
                                          dwp, ap, zp);
        scatter_kernel<<<scatterBlocks, 256>>>(srcp, dstp, ea, ap, zp);
        relu_kernel<<<(NN * 16 + 255) / 256, 256>>>(zp, hp);
    }

    pool_kernel<<<(NN * 16 + 255) / 256, 256>>>(hp, bp, psp, pcp);
    mlp_kernel<<<2, 256>>>(psp, pcp, Wl1, bl1, Wl2, bl2, out);
}

// round 5
// speedup vs baseline: 1.2340x; 1.2340x over previous
#include <cuda_runtime.h>
#include <cstddef>

#define NN 100000
#define EE 1600000
#define GG 512
#define DD 64

// ---------------- scratch (static __device__, no allocation) ----------------
__device__ __align__(256) float g_h[(size_t)NN * DD];
__device__ __align__(256) float g_a[(size_t)NN * DD];
__device__ __align__(256) float g_z[(size_t)NN * DD];
__device__ __align__(256) float g_degw[NN];
__device__ __align__(256) float g_psum[GG * DD];
__device__ __align__(256) float g_pcnt[GG];
__device__ __align__(256) int   g_cnt[NN];
__device__ __align__(256) int   g_rowstart[NN];
__device__ __align__(256) int   g_cursor[NN];
__device__ __align__(256) int2  g_epack[EE];      // (src, w bits), grouped by dst
__device__ __align__(256) int   g_bsum[512];
__device__ __align__(256) int   g_boff[512];
__device__ __align__(256) int   g_batch[NN];
__device__ int   g_eflag;   // nonzero -> edge_index stored as int32
__device__ int   g_bflag;   // nonzero -> batch stored as int32

// ---------------- dtype detection ----------------
// int64 data with values < 2^31 has all-zero odd 32-bit words; int32 data doesn't.
__global__ void detect_kernel(const int* __restrict__ ei32,
                              const int* __restrict__ b32,
                              int* __restrict__ eflag, int* __restrict__ bflag) {
    __shared__ int se, sb;
    if (threadIdx.x == 0) { se = 0; sb = 0; }
    __syncthreads();
    int e = 0, b = 0;
    for (int i = threadIdx.x; i < 1024; i += blockDim.x) {
        e |= ei32[2 * i + 1];
        b |= b32[NN / 2 + 2 * i + 1];
    }
    if (e) atomicOr(&se, 1);
    if (b) atomicOr(&sb, 1);
    __syncthreads();
    if (threadIdx.x == 0) { *eflag = se; *bflag = sb; }
}

__global__ void cvt_batch_kernel(const int* __restrict__ b32,
                                 int* __restrict__ batch,
                                 const int* __restrict__ bflag) {
    int n = blockIdx.x * blockDim.x + threadIdx.x;
    if (n >= NN) return;
    batch[n] = (*bflag) ? b32[n] : b32[2 * n];
}

// ---------------- CSR build: histogram of dst ----------------
__global__ void hist_kernel(const int* __restrict__ ei32,
                            int* __restrict__ cnt,
                            const int* __restrict__ eflag) {
    int e = blockIdx.x * blockDim.x + threadIdx.x;
    if (e >= EE) return;
    int d = (*eflag) ? ei32[EE + e] : ei32[2 * ((size_t)EE + e)];
    atomicAdd(&cnt[d], 1);
}

// ---------------- 3-kernel prefix scan over cnt -> rowstart ----------------
__global__ void scan1_kernel(const int* __restrict__ cnt,
                             int* __restrict__ rowstart, int* __restrict__ bsum) {
    int i = blockIdx.x * 256 + threadIdx.x;
    int v = (i < NN) ? cnt[i] : 0;
    int lane = threadIdx.x & 31, wid = threadIdx.x >> 5;
    int x = v;
    #pragma unroll
    for (int o = 1; o < 32; o <<= 1) {
        int y = __shfl_up_sync(~0u, x, o);
        if (lane >= o) x += y;
    }
    __shared__ int ws[8];
    if (lane == 31) ws[wid] = x;
    __syncthreads();
    if (wid == 0) {
        int y = (lane < 8) ? ws[lane] : 0;
        #pragma unroll
        for (int o = 1; o < 8; o <<= 1) {
            int z = __shfl_up_sync(~0u, y, o);
            if (lane >= o) y += z;
        }
        if (lane < 8) ws[lane] = y;
    }
    __syncthreads();
    int incl = x + (wid > 0 ? ws[wid - 1] : 0);
    if (i < NN) rowstart[i] = incl - v;
    if (threadIdx.x == 255) bsum[blockIdx.x] = incl;
}

__global__ void scan2_kernel(const int* __restrict__ bsum, int* __restrict__ boff,
                             int nblocks) {
    int i = threadIdx.x;  // 512 threads
    int v = (i < nblocks) ? bsum[i] : 0;
    int lane = i & 31, wid = i >> 5;
    int x = v;
    #pragma unroll
    for (int o = 1; o < 32; o <<= 1) {
        int y = __shfl_up_sync(~0u, x, o);
        if (lane >= o) x += y;
    }
    __shared__ int ws[16];
    if (lane == 31) ws[wid] = x;
    __syncthreads();
    if (wid == 0) {
        int y = (lane < 16) ? ws[lane] : 0;
        #pragma unroll
        for (int o = 1; o < 16; o <<= 1) {
            int z = __shfl_up_sync(~0u, y, o);
            if (lane >= o) y += z;
        }
        if (lane < 16) ws[lane] = y;
    }
    __syncthreads();
    int incl = x + (wid > 0 ? ws[wid - 1] : 0);
    if (i < nblocks) boff[i] = incl - v;
}

__global__ void scan3_kernel(int* __restrict__ rowstart, int* __restrict__ cursor,
                             const int* __restrict__ boff) {
    int i = blockIdx.x * 256 + threadIdx.x;
    if (i >= NN) return;
    int r = rowstart[i] + boff[blockIdx.x];
    rowstart[i] = r;
    cursor[i] = r;
}

// ---------------- CSR fill: epack[pos] = (src, w) grouped by dst ----------------
__global__ void fill_kernel(const int* __restrict__ ei32,
                            const float* __restrict__ ea,
                            int* __restrict__ cursor,
                            int2* __restrict__ epack,
                            const int* __restrict__ eflag) {
    int e = blockIdx.x * blockDim.x + threadIdx.x;
    if (e >= EE) return;
    int s, d;
    if (*eflag) {
        s = ei32[e];
        d = ei32[EE + e];
    } else {
        s = ei32[2 * (size_t)e];
        d = ei32[2 * ((size_t)EE + e)];
    }
    int pos = atomicAdd(&cursor[d], 1);
    epack[pos] = make_int2(s, __float_as_int(ea[e]));
}

// ---------------- deg_w from CSR (no atomics) ----------------
__global__ void degw_kernel(const int* __restrict__ rowstart,
                            const int* __restrict__ cnt,
                            const int2* __restrict__ epack,
                            float* __restrict__ degw) {
    int n = blockIdx.x * blockDim.x + threadIdx.x;
    if (n >= NN) return;
    int s = rowstart[n], c = cnt[n];
    float sum = 0.f;
    for (int j = 0; j < c; j++) sum += __int_as_float(epack[s + j].y);
    degw[n] = sum;
}

// ---------------- h = x @ W_emb + b_emb ----------------
__global__ void embed_kernel(const float* __restrict__ x,
                             const float* __restrict__ Wemb,
                             const float* __restrict__ bemb,
                             float* __restrict__ h) {
    int t = blockIdx.x * blockDim.x + threadIdx.x;
    if (t >= NN * 16) return;
    int n = t >> 4;
    int q = t & 15;
    float4 xv = ((const float4*)x)[n];
    const float4* W4 = (const float4*)Wemb;
    float4 w0 = W4[0 * 16 + q];
    float4 w1 = W4[1 * 16 + q];
    float4 w2 = W4[2 * 16 + q];
    float4 w3 = W4[3 * 16 + q];
    float4 bb = ((const float4*)bemb)[q];
    float4 o;
    o.x = bb.x + xv.x * w0.x + xv.y * w1.x + xv.z * w2.x + xv.w * w3.x;
    o.y = bb.y + xv.x * w0.y + xv.y * w1.y + xv.z * w2.y + xv.w * w3.y;
    o.z = bb.z + xv.x * w0.z + xv.y * w1.z + xv.z * w2.z + xv.w * w3.z;
    o.w = bb.w + xv.x * w0.w + xv.y * w1.w + xv.z * w2.w + xv.w * w3.w;
    ((float4*)h)[(size_t)n * 16 + q] = o;
}

// ---------------- fused per-layer GEMMs (f32x2 packed) ----------------
// a = h@W1 + b1 ; z = h@W3 + b3 - deg_w ⊙ (h@W2)
__global__ __launch_bounds__(512) void gemm3_kernel(
    const float* __restrict__ h,
    const float* __restrict__ W1, const float* __restrict__ b1,
    const float* __restrict__ W2,
    const float* __restrict__ W3, const float* __restrict__ b3,
    const float* __restrict__ degw,
    float* __restrict__ a_out, float* __restrict__ z_out) {
    __shared__ __align__(16) float hT[64][128];
    __shared__ __align__(16) float sW[64][64];
    const int tid = threadIdx.x;
    const int nodeBase = blockIdx.x * 128;

    {
        const int n = tid & 127;
        const int kq = tid >> 7;
        const int gn = nodeBase + n;
        #pragma unroll
        for (int kk = 0; kk < 4; kk++) {
            const int k4 = kq * 16 + kk * 4;
            float4 v = make_float4(0.f, 0.f, 0.f, 0.f);
            if (gn < NN) v = *(const float4*)(h + (size_t)gn * 64 + k4);
            hT[k4 + 0][n] = v.x;
            hT[k4 + 1][n] = v.y;
            hT[k4 + 2][n] = v.z;
            hT[k4 + 3][n] = v.w;
        }
    }

    const int tx = tid & 63;
    const int ty = tid >> 6;
    const int nb = ty * 16;

    unsigned long long bacc[8];

    #pragma unroll 1
    for (int m = 0; m < 3; m++) {
        const float* Wm = (m == 0) ? W1 : (m == 1) ? W2 : W3;
        __syncthreads();
        #pragma unroll
        for (int i = 0; i < 2; i++)
            ((float4*)sW)[tid + i * 512] = ((const float4*)Wm)[tid + i * 512];
        __syncthreads();

        unsigned long long acc[8];
        #pragma unroll
        for (int p = 0; p < 8; p++) acc[p] = 0ULL;

        #pragma unroll 8
        for (int k = 0; k < 64; k++) {
            float w = sW[k][tx];
            unsigned long long ws;
            asm("mov.b64 %0, {%1, %1};" : "=l"(ws) : "f"(w));
            #pragma unroll
            for (int i = 0; i < 4; i++) {
                ulonglong2 hv = *(const ulonglong2*)&hT[k][nb + 4 * i];
                asm("fma.rn.f32x2 %0, %1, %2, %0;" : "+l"(acc[2 * i])     : "l"(ws), "l"(hv.x));
                asm("fma.rn.f32x2 %0, %1, %2, %0;" : "+l"(acc[2 * i + 1]) : "l"(ws), "l"(hv.y));
            }
        }

        if (m == 0) {
            const float bias = b1[tx];
            #pragma unroll
            for (int p = 0; p < 8; p++) {
                float f0, f1;
                asm("mov.b64 {%0, %1}, %2;" : "=f"(f0), "=f"(f1) : "l"(acc[p]));
                const int n = nodeBase + nb + 2 * p;
                if (n < NN)     a_out[(size_t)n * 64 + tx]       = f0 + bias;
                if (n + 1 < NN) a_out[(size_t)(n + 1) * 64 + tx] = f1 + bias;
            }
        } else if (m == 1) {
            #pragma unroll
            for (int p = 0; p < 8; p++) bacc[p] = acc[p];
        } else {
            const float bias = b3[tx];
            #pragma unroll
            for (int p = 0; p < 8; p++) {
                float f0, f1, g0, g1;
                asm("mov.b64 {%0, %1}, %2;" : "=f"(f0), "=f"(f1) : "l"(acc[p]));
                asm("mov.b64 {%0, %1}, %2;" : "=f"(g0), "=f"(g1) : "l"(bacc[p]));
                const int n = nodeBase + nb + 2 * p;
                if (n < NN) {
                    float dw = degw[n];
                    z_out[(size_t)n * 64 + tx] = f0 + bias - dw * g0;
                }
                if (n + 1 < NN) {
                    float dw = degw[n + 1];
                    z_out[(size_t)(n + 1) * 64 + tx] = f1 + bias - dw * g1;
                }
            }
        }
    }
}

// ---------------- gather: h[n] = relu(z[n] + sum_{e->n} w_e * a[src_e]) ----------------
// 16 lanes per node (float4 each). No atomics. Optionally fuses mean-pool reduction.
__global__ __launch_bounds__(256, 3) void gather_kernel(
                              const int* __restrict__ rowstart,
                              const int* __restrict__ cnt,
                              const int2* __restrict__ epack,
                              const float* __restrict__ a,
                              const float* __restrict__ z,
                              float* __restrict__ h,
                              const int* __restrict__ batch,
                              float* __restrict__ psum,
                              float* __restrict__ pcnt,
                              int do_pool) {
    int t = blockIdx.x * blockDim.x + threadIdx.x;
    int n = t >> 4;
    if (n >= NN) return;
    int lane = t & 15;
    int s = __ldg(rowstart + n);
    int c = __ldg(cnt + n);
    const float4* a4 = (const float4*)a;
    float4 acc = __ldg((const float4*)z + (size_t)n * 16 + lane);

    int j = 0;
    for (; j + 2 <= c; j += 2) {
        int2 p0 = __ldg(epack + s + j);
        int2 p1 = __ldg(epack + s + j + 1);
        float w0 = __int_as_float(p0.y);
        float w1 = __int_as_float(p1.y);
        float4 v0 = __ldg(a4 + (size_t)p0.x * 16 + lane);
        float4 v1 = __ldg(a4 + (size_t)p1.x * 16 + lane);
        acc.x = fmaf(w0, v0.x, acc.x); acc.y = fmaf(w0, v0.y, acc.y);
        acc.z = fmaf(w0, v0.z, acc.z); acc.w = fmaf(w0, v0.w, acc.w);
        acc.x = fmaf(w1, v1.x, acc.x); acc.y = fmaf(w1, v1.y, acc.y);
        acc.z = fmaf(w1, v1.z, acc.z); acc.w = fmaf(w1, v1.w, acc.w);
    }
    if (j < c) {
        int2 p0 = __ldg(epack + s + j);
        float w0 = __int_as_float(p0.y);
        float4 v0 = __ldg(a4 + (size_t)p0.x * 16 + lane);
        acc.x = fmaf(w0, v0.x, acc.x); acc.y = fmaf(w0, v0.y, acc.y);
        acc.z = fmaf(w0, v0.z, acc.z); acc.w = fmaf(w0, v0.w, acc.w);
    }

    acc.x = fmaxf(acc.x, 0.f); acc.y = fmaxf(acc.y, 0.f);
    acc.z = fmaxf(acc.z, 0.f); acc.w = fmaxf(acc.w, 0.f);
    ((float4*)h)[(size_t)n * 16 + lane] = acc;

    if (do_pool) {
        int g = __ldg(batch + n);
        float* p = psum + (size_t)g * 64 + lane * 4;
        asm volatile("red.global.add.v4.f32 [%0], {%1, %2, %3, %4};"
                     :: "l"(p), "f"(acc.x), "f"(acc.y), "f"(acc.z), "f"(acc.w) : "memory");
        if (lane == 0)
            asm volatile("red.global.add.f32 [%0], %1;" :: "l"(pcnt + g), "f"(1.0f) : "memory");
    }
}

// ---------------- final MLP head ----------------
__global__ void mlp_kernel(const float* __restrict__ psum,
                           const float* __restrict__ pcnt,
                           const float* __restrict__ Wl1, const float* __restrict__ bl1,
                           const float* __restrict__ Wl2, const float* __restrict__ bl2,
                           float* __restrict__ out) {
    __shared__ float sW1[64 * 32];
    __shared__ float sW2[32 * 3];
    __shared__ float sb1[32];
    __shared__ float sb2[3];
    int tid = threadIdx.x;
    for (int i = tid; i < 64 * 32; i += blockDim.x) sW1[i] = Wl1[i];
    for (int i = tid; i < 32 * 3; i += blockDim.x) sW2[i] = Wl2[i];
    if (tid < 32) sb1[tid] = bl1[tid];
    if (tid < 3) sb2[tid] = bl2[tid];
    __syncthreads();

    int g = blockIdx.x * blockDim.x + tid;
    if (g >= GG) return;
    float inv = 1.0f / fmaxf(pcnt[g], 1.0f);
    float hid[32];
    #pragma unroll
    for (int j = 0; j < 32; j++) hid[j] = sb1[j];
    #pragma unroll 8
    for (int k = 0; k < 64; k++) {
        float xv = psum[(size_t)g * 64 + k] * inv;
        #pragma unroll
        for (int j = 0; j < 32; j++) hid[j] += xv * sW1[k * 32 + j];
    }
    #pragma unroll
    for (int j = 0; j < 32; j++) hid[j] = fmaxf(hid[j], 0.f);
    #pragma unroll
    for (int c = 0; c < 3; c++) {
        float o = sb2[c];
        #pragma unroll
        for (int j = 0; j < 32; j++) o += hid[j] * sW2[j * 3 + c];
        out[g * 3 + c] = o;
    }
}

// ---------------- launch ----------------
extern "C" void kernel_launch(void* const* d_in, const int* in_sizes, int n_in,
                              void* d_out, int out_size) {
    const float* x        = (const float*)d_in[0];
    const int*   ei32     = (const int*)d_in[1];
    const float* ea       = (const float*)d_in[2];
    const int*   b32      = (const int*)d_in[3];
    const float* Wemb     = (const float*)d_in[4];
    const float* bemb     = (const float*)d_in[5];
    const float* W1       = (const float*)d_in[6];
    const float* b1       = (const float*)d_in[7];
    const float* W2       = (const float*)d_in[8];
    const float* W3       = (const float*)d_in[9];
    const float* b3       = (const float*)d_in[10];
    const float* Wl1      = (const float*)d_in[11];
    const float* bl1      = (const float*)d_in[12];
    const float* Wl2      = (const float*)d_in[13];
    const float* bl2      = (const float*)d_in[14];
    float* out = (float*)d_out;

    float *hp, *ap, *zp, *dwp, *psp, *pcp;
    int *cntp, *rsp, *curp, *bsp, *bop, *bp, *efp, *bfp;
    int2* epp;
    cudaGetSymbolAddress((void**)&hp, g_h);
    cudaGetSymbolAddress((void**)&ap, g_a);
    cudaGetSymbolAddress((void**)&zp, g_z);
    cudaGetSymbolAddress((void**)&dwp, g_degw);
    cudaGetSymbolAddress((void**)&psp, g_psum);
    cudaGetSymbolAddress((void**)&pcp, g_pcnt);
    cudaGetSymbolAddress((void**)&cntp, g_cnt);
    cudaGetSymbolAddress((void**)&rsp, g_rowstart);
    cudaGetSymbolAddress((void**)&curp, g_cursor);
    cudaGetSymbolAddress((void**)&bsp, g_bsum);
    cudaGetSymbolAddress((void**)&bop, g_boff);
    cudaGetSymbolAddress((void**)&epp, g_epack);
    cudaGetSymbolAddress((void**)&bp, g_batch);
    cudaGetSymbolAddress((void**)&efp, g_eflag);
    cudaGetSymbolAddress((void**)&bfp, g_bflag);

    cudaMemsetAsync(cntp, 0, NN * sizeof(int));
    cudaMemsetAsync(psp, 0, GG * DD * sizeof(float));
    cudaMemsetAsync(pcp, 0, GG * sizeof(float));

    const int scanBlocks = (NN + 255) / 256;   // 391

    detect_kernel<<<1, 256>>>(ei32, b32, efp, bfp);
    cvt_batch_kernel<<<(NN + 255) / 256, 256>>>(b32, bp, bfp);
    hist_kernel<<<(EE + 255) / 256, 256>>>(ei32, cntp, efp);
    scan1_kernel<<<scanBlocks, 256>>>(cntp, rsp, bsp);
    scan2_kernel<<<1, 512>>>(bsp, bop, scanBlocks);
    scan3_kernel<<<scanBlocks, 256>>>(rsp, curp, bop);
    fill_kernel<<<(EE + 255) / 256, 256>>>(ei32, ea, curp, epp, efp);
    degw_kernel<<<(NN + 255) / 256, 256>>>(rsp, cntp, epp, dwp);

    embed_kernel<<<(NN * 16 + 255) / 256, 256>>>(x, Wemb, bemb, hp);

    const int gemmBlocks = (NN + 127) / 128;
    const int gatherBlocks = (NN * 16 + 255) / 256;

    for (int l = 0; l < 3; l++) {
        gemm3_kernel<<<gemmBlocks, 512>>>(hp,
                                          W1 + (size_t)l * DD * DD, b1 + (size_t)l * DD,
                                          W2 + (size_t)l * DD * DD,
                                          W3 + (size_t)l * DD * DD, b3 + (size_t)l * DD,
                                          dwp, ap, zp);
        gather_kernel<<<gatherBlocks, 256>>>(rsp, cntp, epp, ap, zp, hp,
                                             bp, psp, pcp, (l == 2) ? 1 : 0);
    }

    mlp_kernel<<<2, 256>>>(psp, pcp, Wl1, bl1, Wl2, bl2, out);
}

// round 6
// speedup vs baseline: 1.3121x; 1.0633x over previous
#include <cuda_runtime.h>
#include <cstddef>

#define NN 100000
#define EE 1600000
#define GG 512
#define DD 64

// ---------------- scratch (static __device__, no allocation) ----------------
__device__ __align__(256) float g_h[(size_t)NN * DD];
__device__ __align__(256) float g_a[(size_t)NN * DD];
__device__ __align__(256) float g_z[(size_t)NN * DD];
__device__ __align__(256) float g_degw[NN];
__device__ __align__(256) float g_psum[GG * DD];
__device__ __align__(256) float g_pcnt[GG];
__device__ __align__(256) int   g_cnt[NN];
__device__ __align__(256) int   g_rowstart[NN];
__device__ __align__(256) int   g_cursor[NN];
__device__ __align__(256) int2  g_epack[EE];      // (src, w bits), grouped by dst
__device__ __align__(256) int   g_bsum[512];
__device__ __align__(256) int   g_boff[512];
__device__ __align__(256) int   g_batch[NN];
__device__ int   g_eflag;   // nonzero -> edge_index stored as int32
__device__ int   g_bflag;   // nonzero -> batch stored as int32

// ---------------- dtype detection ----------------
__global__ void detect_kernel(const int* __restrict__ ei32,
                              const int* __restrict__ b32,
                              int* __restrict__ eflag, int* __restrict__ bflag) {
    __shared__ int se, sb;
    if (threadIdx.x == 0) { se = 0; sb = 0; }
    __syncthreads();
    int e = 0, b = 0;
    for (int i = threadIdx.x; i < 1024; i += blockDim.x) {
        e |= ei32[2 * i + 1];
        b |= b32[NN / 2 + 2 * i + 1];
    }
    if (e) atomicOr(&se, 1);
    if (b) atomicOr(&sb, 1);
    __syncthreads();
    if (threadIdx.x == 0) { *eflag = se; *bflag = sb; }
}

__global__ void cvt_batch_kernel(const int* __restrict__ b32,
                                 int* __restrict__ batch,
                                 const int* __restrict__ bflag) {
    int n = blockIdx.x * blockDim.x + threadIdx.x;
    if (n >= NN) return;
    batch[n] = (*bflag) ? b32[n] : b32[2 * n];
}

// ---------------- CSR build: histogram of dst ----------------
__global__ void hist_kernel(const int* __restrict__ ei32,
                            int* __restrict__ cnt,
                            const int* __restrict__ eflag) {
    int e = blockIdx.x * blockDim.x + threadIdx.x;
    if (e >= EE) return;
    int d = (*eflag) ? ei32[EE + e] : ei32[2 * ((size_t)EE + e)];
    atomicAdd(&cnt[d], 1);
}

// ---------------- 3-kernel prefix scan over cnt -> rowstart ----------------
__global__ void scan1_kernel(const int* __restrict__ cnt,
                             int* __restrict__ rowstart, int* __restrict__ bsum) {
    int i = blockIdx.x * 256 + threadIdx.x;
    int v = (i < NN) ? cnt[i] : 0;
    int lane = threadIdx.x & 31, wid = threadIdx.x >> 5;
    int x = v;
    #pragma unroll
    for (int o = 1; o < 32; o <<= 1) {
        int y = __shfl_up_sync(~0u, x, o);
        if (lane >= o) x += y;
    }
    __shared__ int ws[8];
    if (lane == 31) ws[wid] = x;
    __syncthreads();
    if (wid == 0) {
        int y = (lane < 8) ? ws[lane] : 0;
        #pragma unroll
        for (int o = 1; o < 8; o <<= 1) {
            int z = __shfl_up_sync(~0u, y, o);
            if (lane >= o) y += z;
        }
        if (lane < 8) ws[lane] = y;
    }
    __syncthreads();
    int incl = x + (wid > 0 ? ws[wid - 1] : 0);
    if (i < NN) rowstart[i] = incl - v;
    if (threadIdx.x == 255) bsum[blockIdx.x] = incl;
}

__global__ void scan2_kernel(const int* __restrict__ bsum, int* __restrict__ boff,
                             int nblocks) {
    int i = threadIdx.x;  // 512 threads
    int v = (i < nblocks) ? bsum[i] : 0;
    int lane = i & 31, wid = i >> 5;
    int x = v;
    #pragma unroll
    for (int o = 1; o < 32; o <<= 1) {
        int y = __shfl_up_sync(~0u, x, o);
        if (lane >= o) x += y;
    }
    __shared__ int ws[16];
    if (lane == 31) ws[wid] = x;
    __syncthreads();
    if (wid == 0) {
        int y = (lane < 16) ? ws[lane] : 0;
        #pragma unroll
        for (int o = 1; o < 16; o <<= 1) {
            int z = __shfl_up_sync(~0u, y, o);
            if (lane >= o) y += z;
        }
        if (lane < 16) ws[lane] = y;
    }
    __syncthreads();
    int incl = x + (wid > 0 ? ws[wid - 1] : 0);
    if (i < nblocks) boff[i] = incl - v;
}

__global__ void scan3_kernel(int* __restrict__ rowstart, int* __restrict__ cursor,
                             const int* __restrict__ boff) {
    int i = blockIdx.x * 256 + threadIdx.x;
    if (i >= NN) return;
    int r = rowstart[i] + boff[blockIdx.x];
    rowstart[i] = r;
    cursor[i] = r;
}

// ---------------- CSR fill: epack[pos] = (src, w) grouped by dst ----------------
__global__ void fill_kernel(const int* __restrict__ ei32,
                            const float* __restrict__ ea,
                            int* __restrict__ cursor,
                            int2* __restrict__ epack,
                            const int* __restrict__ eflag) {
    int e = blockIdx.x * blockDim.x + threadIdx.x;
    if (e >= EE) return;
    int s, d;
    if (*eflag) {
        s = ei32[e];
        d = ei32[EE + e];
    } else {
        s = ei32[2 * (size_t)e];
        d = ei32[2 * ((size_t)EE + e)];
    }
    int pos = atomicAdd(&cursor[d], 1);
    epack[pos] = make_int2(s, __float_as_int(ea[e]));
}

// ---------------- deg_w from CSR (no atomics) ----------------
__global__ void degw_kernel(const int* __restrict__ rowstart,
                            const int* __restrict__ cnt,
                            const int2* __restrict__ epack,
                            float* __restrict__ degw) {
    int n = blockIdx.x * blockDim.x + threadIdx.x;
    if (n >= NN) return;
    int s = rowstart[n], c = cnt[n];
    float sum = 0.f;
    for (int j = 0; j < c; j++) sum += __int_as_float(epack[s + j].y);
    degw[n] = sum;
}

// ---------------- h = x @ W_emb + b_emb ----------------
__global__ void embed_kernel(const float* __restrict__ x,
                             const float* __restrict__ Wemb,
                             const float* __restrict__ bemb,
                             float* __restrict__ h) {
    int t = blockIdx.x * blockDim.x + threadIdx.x;
    if (t >= NN * 16) return;
    int n = t >> 4;
    int q = t & 15;
    float4 xv = ((const float4*)x)[n];
    const float4* W4 = (const float4*)Wemb;
    float4 w0 = W4[0 * 16 + q];
    float4 w1 = W4[1 * 16 + q];
    float4 w2 = W4[2 * 16 + q];
    float4 w3 = W4[3 * 16 + q];
    float4 bb = ((const float4*)bemb)[q];
    float4 o;
    o.x = bb.x + xv.x * w0.x + xv.y * w1.x + xv.z * w2.x + xv.w * w3.x;
    o.y = bb.y + xv.x * w0.y + xv.y * w1.y + xv.z * w2.y + xv.w * w3.y;
    o.z = bb.z + xv.x * w0.z + xv.y * w1.z + xv.z * w2.z + xv.w * w3.z;
    o.w = bb.w + xv.x * w0.w + xv.y * w1.w + xv.z * w2.w + xv.w * w3.w;
    ((float4*)h)[(size_t)n * 16 + q] = o;
}

// ---------------- fused per-layer GEMMs (f32x2 packed) ----------------
// a = h@W1 + b1 ; z = h@W3 + b3 - deg_w ⊙ (h@W2)   (z stored evict-first)
__global__ __launch_bounds__(512) void gemm3_kernel(
    const float* __restrict__ h,
    const float* __restrict__ W1, const float* __restrict__ b1,
    const float* __restrict__ W2,
    const float* __restrict__ W3, const float* __restrict__ b3,
    const float* __restrict__ degw,
    float* __restrict__ a_out, float* __restrict__ z_out) {
    __shared__ __align__(16) float hT[64][128];
    __shared__ __align__(16) float sW[64][64];
    const int tid = threadIdx.x;
    const int nodeBase = blockIdx.x * 128;

    {
        const int n = tid & 127;
        const int kq = tid >> 7;
        const int gn = nodeBase + n;
        #pragma unroll
        for (int kk = 0; kk < 4; kk++) {
            const int k4 = kq * 16 + kk * 4;
            float4 v = make_float4(0.f, 0.f, 0.f, 0.f);
            if (gn < NN) v = *(const float4*)(h + (size_t)gn * 64 + k4);
            hT[k4 + 0][n] = v.x;
            hT[k4 + 1][n] = v.y;
            hT[k4 + 2][n] = v.z;
            hT[k4 + 3][n] = v.w;
        }
    }

    const int tx = tid & 63;
    const int ty = tid >> 6;
    const int nb = ty * 16;

    unsigned long long bacc[8];

    #pragma unroll 1
    for (int m = 0; m < 3; m++) {
        const float* Wm = (m == 0) ? W1 : (m == 1) ? W2 : W3;
        __syncthreads();
        #pragma unroll
        for (int i = 0; i < 2; i++)
            ((float4*)sW)[tid + i * 512] = ((const float4*)Wm)[tid + i * 512];
        __syncthreads();

        unsigned long long acc[8];
        #pragma unroll
        for (int p = 0; p < 8; p++) acc[p] = 0ULL;

        #pragma unroll 8
        for (int k = 0; k < 64; k++) {
            float w = sW[k][tx];
            unsigned long long ws;
            asm("mov.b64 %0, {%1, %1};" : "=l"(ws) : "f"(w));
            #pragma unroll
            for (int i = 0; i < 4; i++) {
                ulonglong2 hv = *(const ulonglong2*)&hT[k][nb + 4 * i];
                asm("fma.rn.f32x2 %0, %1, %2, %0;" : "+l"(acc[2 * i])     : "l"(ws), "l"(hv.x));
                asm("fma.rn.f32x2 %0, %1, %2, %0;" : "+l"(acc[2 * i + 1]) : "l"(ws), "l"(hv.y));
            }
        }

        if (m == 0) {
            const float bias = b1[tx];
            #pragma unroll
            for (int p = 0; p < 8; p++) {
                float f0, f1;
                asm("mov.b64 {%0, %1}, %2;" : "=f"(f0), "=f"(f1) : "l"(acc[p]));
                const int n = nodeBase + nb + 2 * p;
                if (n < NN)     a_out[(size_t)n * 64 + tx]       = f0 + bias;
                if (n + 1 < NN) a_out[(size_t)(n + 1) * 64 + tx] = f1 + bias;
            }
        } else if (m == 1) {
            #pragma unroll
            for (int p = 0; p < 8; p++) bacc[p] = acc[p];
        } else {
            const float bias = b3[tx];
            #pragma unroll
            for (int p = 0; p < 8; p++) {
                float f0, f1, g0, g1;
                asm("mov.b64 {%0, %1}, %2;" : "=f"(f0), "=f"(f1) : "l"(acc[p]));
                asm("mov.b64 {%0, %1}, %2;" : "=f"(g0), "=f"(g1) : "l"(bacc[p]));
                const int n = nodeBase + nb + 2 * p;
                if (n < NN) {
                    float dw = degw[n];
                    __stcs(&z_out[(size_t)n * 64 + tx], f0 + bias - dw * g0);
                }
                if (n + 1 < NN) {
                    float dw = degw[n + 1];
                    __stcs(&z_out[(size_t)(n + 1) * 64 + tx], f1 + bias - dw * g1);
                }
            }
        }
    }
}

// ---------------- gather: h[n] = relu(z[n] + sum_{e->n} w_e * a[src_e]) ----------------
// 8 lanes per node, 2 float4 per lane -> 4 row loads in flight per thread.
// z read evict-first (single use); a reads default (hot, L2-resident).
__global__ __launch_bounds__(256) void gather_kernel(
                              const int* __restrict__ rowstart,
                              const int* __restrict__ cnt,
                              const int2* __restrict__ epack,
                              const float* __restrict__ a,
                              const float* __restrict__ z,
                              float* __restrict__ h,
                              const int* __restrict__ batch,
                              float* __restrict__ psum,
                              float* __restrict__ pcnt,
                              int do_pool) {
    int t = blockIdx.x * blockDim.x + threadIdx.x;
    int n = t >> 3;
    if (n >= NN) return;
    int lane = t & 7;          // 8 floats each (2 float4)
    int s = __ldg(rowstart + n);
    int c = __ldg(cnt + n);
    const float4* a4 = (const float4*)a;

    const float4* zp4 = (const float4*)z + (size_t)n * 16 + lane * 2;
    float4 acc0 = __ldcs(zp4);
    float4 acc1 = __ldcs(zp4 + 1);

    int j = 0;
    for (; j + 2 <= c; j += 2) {
        int2 p0 = __ldg(epack + s + j);
        int2 p1 = __ldg(epack + s + j + 1);
        float w0 = __int_as_float(p0.y);
        float w1 = __int_as_float(p1.y);
        const float4* r0 = a4 + (size_t)p0.x * 16 + lane * 2;
        const float4* r1 = a4 + (size_t)p1.x * 16 + lane * 2;
        float4 v00 = __ldg(r0);
        float4 v01 = __ldg(r0 + 1);
        float4 v10 = __ldg(r1);
        float4 v11 = __ldg(r1 + 1);
        acc0.x = fmaf(w0, v00.x, acc0.x); acc0.y = fmaf(w0, v00.y, acc0.y);
        acc0.z = fmaf(w0, v00.z, acc0.z); acc0.w = fmaf(w0, v00.w, acc0.w);
        acc1.x = fmaf(w0, v01.x, acc1.x); acc1.y = fmaf(w0, v01.y, acc1.y);
        acc1.z = fmaf(w0, v01.z, acc1.z); acc1.w = fmaf(w0, v01.w, acc1.w);
        acc0.x = fmaf(w1, v10.x, acc0.x); acc0.y = fmaf(w1, v10.y, acc0.y);
        acc0.z = fmaf(w1, v10.z, acc0.z); acc0.w = fmaf(w1, v10.w, acc0.w);
        acc1.x = fmaf(w1, v11.x, acc1.x); acc1.y = fmaf(w1, v11.y, acc1.y);
        acc1.z = fmaf(w1, v11.z, acc1.z); acc1.w = fmaf(w1, v11.w, acc1.w);
    }
    if (j < c) {
        int2 p0 = __ldg(epack + s + j);
        float w0 = __int_as_float(p0.y);
        const float4* r0 = a4 + (size_t)p0.x * 16 + lane * 2;
        float4 v00 = __ldg(r0);
        float4 v01 = __ldg(r0 + 1);
        acc0.x = fmaf(w0, v00.x, acc0.x); acc0.y = fmaf(w0, v00.y, acc0.y);
        acc0.z = fmaf(w0, v00.z, acc0.z); acc0.w = fmaf(w0, v00.w, acc0.w);
        acc1.x = fmaf(w0, v01.x, acc1.x); acc1.y = fmaf(w0, v01.y, acc1.y);
        acc1.z = fmaf(w0, v01.z, acc1.z); acc1.w = fmaf(w0, v01.w, acc1.w);
    }

    acc0.x = fmaxf(acc0.x, 0.f); acc0.y = fmaxf(acc0.y, 0.f);
    acc0.z = fmaxf(acc0.z, 0.f); acc0.w = fmaxf(acc0.w, 0.f);
    acc1.x = fmaxf(acc1.x, 0.f); acc1.y = fmaxf(acc1.y, 0.f);
    acc1.z = fmaxf(acc1.z, 0.f); acc1.w = fmaxf(acc1.w, 0.f);
    float4* hp4 = (float4*)h + (size_t)n * 16 + lane * 2;
    hp4[0] = acc0;
    hp4[1] = acc1;

    if (do_pool) {
        int g = __ldg(batch + n);
        float* p = psum + (size_t)g * 64 + lane * 8;
        asm volatile("red.global.add.v4.f32 [%0], {%1, %2, %3, %4};"
                     :: "l"(p), "f"(acc0.x), "f"(acc0.y), "f"(acc0.z), "f"(acc0.w) : "memory");
        asm volatile("red.global.add.v4.f32 [%0], {%1, %2, %3, %4};"
                     :: "l"(p + 4), "f"(acc1.x), "f"(acc1.y), "f"(acc1.z), "f"(acc1.w) : "memory");
        if (lane == 0)
            asm volatile("red.global.add.f32 [%0], %1;" :: "l"(pcnt + g), "f"(1.0f) : "memory");
    }
}

// ---------------- final MLP head ----------------
__global__ void mlp_kernel(const float* __restrict__ psum,
                           const float* __restrict__ pcnt,
                           const float* __restrict__ Wl1, const float* __restrict__ bl1,
                           const float* __restrict__ Wl2, const float* __restrict__ bl2,
                           float* __restrict__ out) {
    __shared__ float sW1[64 * 32];
    __shared__ float sW2[32 * 3];
    __shared__ float sb1[32];
    __shared__ float sb2[3];
    int tid = threadIdx.x;
    for (int i = tid; i < 64 * 32; i += blockDim.x) sW1[i] = Wl1[i];
    for (int i = tid; i < 32 * 3; i += blockDim.x) sW2[i] = Wl2[i];
    if (tid < 32) sb1[tid] = bl1[tid];
    if (tid < 3) sb2[tid] = bl2[tid];
    __syncthreads();

    int g = blockIdx.x * blockDim.x + tid;
    if (g >= GG) return;
    float inv = 1.0f / fmaxf(pcnt[g], 1.0f);
    float hid[32];
    #pragma unroll
    for (int j = 0; j < 32; j++) hid[j] = sb1[j];
    #pragma unroll 8
    for (int k = 0; k < 64; k++) {
        float xv = psum[(size_t)g * 64 + k] * inv;
        #pragma unroll
        for (int j = 0; j < 32; j++) hid[j] += xv * sW1[k * 32 + j];
    }
    #pragma unroll
    for (int j = 0; j < 32; j++) hid[j] = fmaxf(hid[j], 0.f);
    #pragma unroll
    for (int c = 0; c < 3; c++) {
        float o = sb2[c];
        #pragma unroll
        for (int j = 0; j < 32; j++) o += hid[j] * sW2[j * 3 + c];
        out[g * 3 + c] = o;
    }
}

// ---------------- launch ----------------
extern "C" void kernel_launch(void* const* d_in, const int* in_sizes, int n_in,
                              void* d_out, int out_size) {
    const float* x        = (const float*)d_in[0];
    const int*   ei32     = (const int*)d_in[1];
    const float* ea       = (const float*)d_in[2];
    const int*   b32      = (const int*)d_in[3];
    const float* Wemb     = (const float*)d_in[4];
    const float* bemb     = (const float*)d_in[5];
    const float* W1       = (const float*)d_in[6];
    const float* b1       = (const float*)d_in[7];
    const float* W2       = (const float*)d_in[8];
    const float* W3       = (const float*)d_in[9];
    const float* b3       = (const float*)d_in[10];
    const float* Wl1      = (const float*)d_in[11];
    const float* bl1      = (const float*)d_in[12];
    const float* Wl2      = (const float*)d_in[13];
    const float* bl2      = (const float*)d_in[14];
    float* out = (float*)d_out;

    float *hp, *ap, *zp, *dwp, *psp, *pcp;
    int *cntp, *rsp, *curp, *bsp, *bop, *bp, *efp, *bfp;
    int2* epp;
    cudaGetSymbolAddress((void**)&hp, g_h);
    cudaGetSymbolAddress((void**)&ap, g_a);
    cudaGetSymbolAddress((void**)&zp, g_z);
    cudaGetSymbolAddress((void**)&dwp, g_degw);
    cudaGetSymbolAddress((void**)&psp, g_psum);
    cudaGetSymbolAddress((void**)&pcp, g_pcnt);
    cudaGetSymbolAddress((void**)&cntp, g_cnt);
    cudaGetSymbolAddress((void**)&rsp, g_rowstart);
    cudaGetSymbolAddress((void**)&curp, g_cursor);
    cudaGetSymbolAddress((void**)&bsp, g_bsum);
    cudaGetSymbolAddress((void**)&bop, g_boff);
    cudaGetSymbolAddress((void**)&epp, g_epack);
    cudaGetSymbolAddress((void**)&bp, g_batch);
    cudaGetSymbolAddress((void**)&efp, g_eflag);
    cudaGetSymbolAddress((void**)&bfp, g_bflag);

    cudaMemsetAsync(cntp, 0, NN * sizeof(int));
    cudaMemsetAsync(psp, 0, GG * DD * sizeof(float));
    cudaMemsetAsync(pcp, 0, GG * sizeof(float));

    const int scanBlocks = (NN + 255) / 256;   // 391

    detect_kernel<<<1, 256>>>(ei32, b32, efp, bfp);
    cvt_batch_kernel<<<(NN + 255) / 256, 256>>>(b32, bp, bfp);
    hist_kernel<<<(EE + 255) / 256, 256>>>(ei32, cntp, efp);
    scan1_kernel<<<scanBlocks, 256>>>(cntp, rsp, bsp);
    scan2_kernel<<<1, 512>>>(bsp, bop, scanBlocks);
    scan3_kernel<<<scanBlocks, 256>>>(rsp, curp, bop);
    fill_kernel<<<(EE + 255) / 256, 256>>>(ei32, ea, curp, epp, efp);
    degw_kernel<<<(NN + 255) / 256, 256>>>(rsp, cntp, epp, dwp);

    embed_kernel<<<(NN * 16 + 255) / 256, 256>>>(x, Wemb, bemb, hp);

    const int gemmBlocks = (NN + 127) / 128;
    const int gatherBlocks = (NN * 8 + 255) / 256;

    for (int l = 0; l < 3; l++) {
        gemm3_kernel<<<gemmBlocks, 512>>>(hp,
                                          W1 + (size_t)l * DD * DD, b1 + (size_t)l * DD,
                                          W2 + (size_t)l * DD * DD,
                                          W3 + (size_t)l * DD * DD, b3 + (size_t)l * DD,
                                          dwp, ap, zp);
        gather_kernel<<<gatherBlocks, 256>>>(rsp, cntp, epp, ap, zp, hp,
                                             bp, psp, pcp, (l == 2) ? 1 : 0);
    }

    mlp_kernel<<<2, 256>>>(psp, pcp, Wl1, bl1, Wl2, bl2, out);
}